// round 7
// baseline (speedup 1.0000x reference)
#include <cuda_runtime.h>
#include <cuda_fp16.h>
#include <stdint.h>

// MessageFunction via mma.sync m16n8k16 fp16 (fp32 accum), persistent CTAs.
// R7: each warp owns 64 edge-rows (TILE=512) -> every W2 B-fragment load
//     feeds 4 MMAs (halves smem traffic per edge, 2x ILP). cp.async.cg
//     double-buffered staging (no staging registers). Padded strides
//     (20 floats) for conflict-free fragment LDS.

#define TPB   256
#define TILE  512
#define ESTR  20
#define HSTR  20

// ---- smem float offsets ----
#define OF_W2F 0       // 8192 fl: W2 B-frags uint2[ks(4)][ntg(32)][lane(32)]
#define OF_W1F 8192    // 512 fl : W1 B-frags uint2[nt(8)][lane(32)]
#define OF_B1  8704    // 64
#define OF_B2  8768    // 256
#define OF_E   9024    // 2 x 512*ESTR fl : e tile f32, double buffered
#define OF_H   29504   // 2 x 512*HSTR fl : h tile f32, double buffered
#define SMEM_FLOATS 49984   // 199936 bytes

__device__ __forceinline__ uint32_t pack_h2(float a, float b) {
    __half2 h = __floats2half2_rn(a, b);
    return *(uint32_t*)&h;
}
__device__ __forceinline__ uint32_t smem_u32(const void* p) {
    uint32_t a;
    asm("{ .reg .u64 t; cvta.to.shared.u64 t, %1; cvt.u32.u64 %0, t; }" : "=r"(a) : "l"(p));
    return a;
}

// Not volatile: pure register computation; let ptxas pipeline it.
#define MMA_F16(d, a, b0, b1) \
    asm("mma.sync.aligned.m16n8k16.row.col.f32.f16.f16.f32 " \
        "{%0,%1,%2,%3}, {%4,%5,%6,%7}, {%8,%9}, {%0,%1,%2,%3};" \
        : "+f"((d)[0]), "+f"((d)[1]), "+f"((d)[2]), "+f"((d)[3]) \
        : "r"((a)[0]), "r"((a)[1]), "r"((a)[2]), "r"((a)[3]), \
          "r"(b0), "r"(b1))

__device__ __forceinline__ void red_add_v2(float* p, float a, float b) {
    asm volatile("red.global.add.v2.f32 [%0], {%1,%2};"
                 :: "l"(p), "f"(a), "f"(b) : "memory");
}
__device__ __forceinline__ void cp16(uint32_t s, const void* g) {
    asm volatile("cp.async.cg.shared.global [%0], [%1], 16;" :: "r"(s), "l"(g));
}
__device__ __forceinline__ void cp_commit() {
    asm volatile("cp.async.commit_group;" ::: "memory");
}
__device__ __forceinline__ void cp_wait_all() {
    asm volatile("cp.async.wait_group 0;" ::: "memory");
}

extern "C" __global__ void __launch_bounds__(TPB, 1)
msg_mma_kernel(const int* __restrict__ index_v,
               const float* __restrict__ h_w,
               const float* __restrict__ e_vw,
               const float* __restrict__ W1,
               const float* __restrict__ b1,
               const float* __restrict__ W2,
               const float* __restrict__ b2,
               float* __restrict__ out,
               int n_edge) {
    extern __shared__ float sm[];
    const uint32_t sb = smem_u32(sm);
    const int tid  = threadIdx.x;
    const int warp = tid >> 5;
    const int lane = tid & 31;
    const int q = lane & 3;       // quad col
    const int g = lane >> 2;      // group row

    // ================= stage weight fragments (once per CTA) =================
    for (int s = tid; s < 4096; s += TPB) {
        int ks = s >> 10, rest = s & 1023, ntg = rest >> 5, ln = rest & 31;
        int qq = ln & 3, gg = ln >> 2;
        int n = ntg * 8 + gg, r0 = ks * 16 + 2 * qq;
        uint2 b;
        b.x = pack_h2(W2[(r0)     * 256 + n], W2[(r0 + 1) * 256 + n]);
        b.y = pack_h2(W2[(r0 + 8) * 256 + n], W2[(r0 + 9) * 256 + n]);
        ((uint2*)(sm + OF_W2F))[s] = b;
    }
    for (int s = tid; s < 256; s += TPB) {
        int nt = s >> 5, ln = s & 31;
        int qq = ln & 3, gg = ln >> 2;
        int n = nt * 8 + gg;
        uint2 b;
        b.x = pack_h2(W1[(2 * qq)     * 64 + n], W1[(2 * qq + 1) * 64 + n]);
        b.y = pack_h2(W1[(2 * qq + 8) * 64 + n], W1[(2 * qq + 9) * 64 + n]);
        ((uint2*)(sm + OF_W1F))[s] = b;
    }
    if (tid < 64)  sm[OF_B1 + tid] = b1[tid];
    if (tid < 256) sm[OF_B2 + tid] = b2[tid];

    const int ntiles = (n_edge + TILE - 1) / TILE;

    // ---- async stage of tile t into buffer bufsel ----
    auto stage = [&](int t, int bufsel) {
        const int base = t * TILE;
        const int rem  = n_edge - base;
        const uint32_t eb = sb + (OF_E + bufsel * TILE * ESTR) * 4;
        const uint32_t hb = sb + (OF_H + bufsel * TILE * HSTR) * 4;
#pragma unroll
        for (int rwi = 0; rwi < 2; rwi++) {
            const int rw = tid + rwi * TPB;
            const int sr = rw < rem ? rw : rem - 1;
            const char* ep = (const char*)(e_vw + (size_t)(base + sr) * 16);
            const char* hp = (const char*)(h_w  + (size_t)(base + sr) * 16);
            const uint32_t de = eb + rw * (ESTR * 4);
            const uint32_t dh = hb + rw * (HSTR * 4);
#pragma unroll
            for (int i = 0; i < 4; i++) {
                cp16(de + 16 * i, ep + 16 * i);
                cp16(dh + 16 * i, hp + 16 * i);
            }
        }
        cp_commit();
    };

    // ---- prologue: stage first tile into buffer 0 ----
    if (blockIdx.x < ntiles) stage(blockIdx.x, 0);
    cp_wait_all();
    __syncthreads();

    int it = 0;
    for (int t = blockIdx.x; t < ntiles; t += gridDim.x, it++) {
        const int base = t * TILE;
        const int buf  = it & 1;
        const float* E = sm + OF_E + buf * TILE * ESTR;
        const float* H = sm + OF_H + buf * TILE * HSTR;

        // ---- GEMM1 in two passes of 2 sub-tiles; build A-frags ha[4][4][4] ----
        uint32_t ha[4][4][4];
#pragma unroll
        for (int p = 0; p < 2; p++) {
            uint32_t ea[2][4];
#pragma unroll
            for (int ml = 0; ml < 2; ml++) {
                const int r0 = warp * 64 + (p * 2 + ml) * 16 + g;
                const float* Er = E + r0 * ESTR;
                float2 c0 = *(const float2*)(Er + 2 * q);
                float2 c1 = *(const float2*)(Er + 8 * ESTR + 2 * q);
                float2 c2 = *(const float2*)(Er + 8 + 2 * q);
                float2 c3 = *(const float2*)(Er + 8 * ESTR + 8 + 2 * q);
                ea[ml][0] = pack_h2(c0.x, c0.y);
                ea[ml][1] = pack_h2(c1.x, c1.y);
                ea[ml][2] = pack_h2(c2.x, c2.y);
                ea[ml][3] = pack_h2(c3.x, c3.y);
            }
            float acc1[2][8][4];
#pragma unroll
            for (int ml = 0; ml < 2; ml++)
#pragma unroll
                for (int nt = 0; nt < 8; nt++)
#pragma unroll
                    for (int r = 0; r < 4; r++) acc1[ml][nt][r] = 0.0f;
#pragma unroll
            for (int nt = 0; nt < 8; nt++) {
                uint2 b = ((const uint2*)(sm + OF_W1F))[nt * 32 + lane];
                MMA_F16(acc1[0][nt], ea[0], b.x, b.y);
                MMA_F16(acc1[1][nt], ea[1], b.x, b.y);
            }
#pragma unroll
            for (int ml = 0; ml < 2; ml++)
#pragma unroll
                for (int nt = 0; nt < 8; nt++) {
                    float2 bb = *(const float2*)(sm + OF_B1 + nt * 8 + 2 * q);
                    float v0 = fmaxf(acc1[ml][nt][0] + bb.x, 0.0f);
                    float v1 = fmaxf(acc1[ml][nt][1] + bb.y, 0.0f);
                    float v2 = fmaxf(acc1[ml][nt][2] + bb.x, 0.0f);
                    float v3 = fmaxf(acc1[ml][nt][3] + bb.y, 0.0f);
                    int ks = nt >> 1, hi = (nt & 1) * 2;
                    ha[p * 2 + ml][ks][hi]     = pack_h2(v0, v1);
                    ha[p * 2 + ml][ks][hi + 1] = pack_h2(v2, v3);
                }
        }

        // ---- h regs + nodes (reads current H) ----
        float hreg[4][2][4];
        int   node[4][2];
        bool  vld[4][2];
#pragma unroll
        for (int mt = 0; mt < 4; mt++)
#pragma unroll
            for (int rr = 0; rr < 2; rr++) {
                const int row = warp * 64 + mt * 16 + g + rr * 8;
                const float* Hr = H + row * HSTR;
                float2 h0 = *(const float2*)(Hr + 2 * q);
                float2 h1 = *(const float2*)(Hr + 8 + 2 * q);
                hreg[mt][rr][0] = h0.x; hreg[mt][rr][1] = h0.y;
                hreg[mt][rr][2] = h1.x; hreg[mt][rr][3] = h1.y;
                const int ge = base + row;
                vld[mt][rr]  = ge < n_edge;
                node[mt][rr] = vld[mt][rr] ? __ldg(index_v + ge) : 0;
            }

        // ---- kick off next-tile async staging into other buffer ----
        const int tn = t + gridDim.x;
        if (tn < ntiles) stage(tn, buf ^ 1);

        // ---- GEMM2 + epilogue, 8 chunks of 32 cols (m = 2c, 2c+1) ----
#pragma unroll
        for (int c = 0; c < 8; c++) {
            float acc[4][4][4];
#pragma unroll
            for (int mt = 0; mt < 4; mt++)
#pragma unroll
                for (int nt = 0; nt < 4; nt++)
#pragma unroll
                    for (int r = 0; r < 4; r++) acc[mt][nt][r] = 0.0f;
#pragma unroll
            for (int ks = 0; ks < 4; ks++)
#pragma unroll
                for (int nt = 0; nt < 4; nt++) {
                    uint2 b = ((const uint2*)(sm + OF_W2F))[(ks * 32 + c * 4 + nt) * 32 + lane];
                    MMA_F16(acc[0][nt], ha[0][ks], b.x, b.y);
                    MMA_F16(acc[1][nt], ha[1][ks], b.x, b.y);
                    MMA_F16(acc[2][nt], ha[2][ks], b.x, b.y);
                    MMA_F16(acc[3][nt], ha[3][ks], b.x, b.y);
                }
            float pacc[4][2][2];
#pragma unroll
            for (int mt = 0; mt < 4; mt++)
#pragma unroll
                for (int rr = 0; rr < 2; rr++) {
                    pacc[mt][rr][0] = 0.0f; pacc[mt][rr][1] = 0.0f;
                }
#pragma unroll
            for (int nt = 0; nt < 4; nt++) {
                const int ntg = c * 4 + nt;
                float2 bb = *(const float2*)(sm + OF_B2 + ntg * 8 + 2 * q);
                const int hb = (nt & 1) * 2;
                const int ml = nt >> 1;
#pragma unroll
                for (int mt = 0; mt < 4; mt++) {
                    pacc[mt][0][ml] = fmaf(acc[mt][nt][0] + bb.x, hreg[mt][0][hb],     pacc[mt][0][ml]);
                    pacc[mt][0][ml] = fmaf(acc[mt][nt][1] + bb.y, hreg[mt][0][hb + 1], pacc[mt][0][ml]);
                    pacc[mt][1][ml] = fmaf(acc[mt][nt][2] + bb.x, hreg[mt][1][hb],     pacc[mt][1][ml]);
                    pacc[mt][1][ml] = fmaf(acc[mt][nt][3] + bb.y, hreg[mt][1][hb + 1], pacc[mt][1][ml]);
                }
            }
#pragma unroll
            for (int mt = 0; mt < 4; mt++)
#pragma unroll
                for (int rr = 0; rr < 2; rr++) {
#pragma unroll
                    for (int ml = 0; ml < 2; ml++) {
                        float v = pacc[mt][rr][ml];
                        v += __shfl_xor_sync(0xFFFFFFFFu, v, 1);
                        v += __shfl_xor_sync(0xFFFFFFFFu, v, 2);
                        pacc[mt][rr][ml] = v;
                    }
                    if (q == 0 && vld[mt][rr]) {
                        red_add_v2(out + (size_t)node[mt][rr] * 16 + 2 * c,
                                   pacc[mt][rr][0], pacc[mt][rr][1]);
                    }
                }
        }

        cp_wait_all();     // next-tile staging landed
        __syncthreads();   // all reads of current buffers done CTA-wide
    }
}

// ---------------- launch ----------------
extern "C" void kernel_launch(void* const* d_in, const int* in_sizes, int n_in,
                              void* d_out, int out_size) {
    const int*   index_v = nullptr;
    const float* h_w = nullptr;
    const float* e_vw = nullptr;
    const float* W1 = nullptr;
    const float* b1 = nullptr;
    const float* W2 = nullptr;
    const float* b2 = nullptr;

    int big_idx[8]; long long big_sz[8]; int nb = 0;
    for (int i = 0; i < n_in; i++) {
        long long s = in_sizes[i];
        if (s == 1024)       W1 = (const float*)d_in[i];
        else if (s == 64)    b1 = (const float*)d_in[i];
        else if (s == 16384) W2 = (const float*)d_in[i];
        else if (s == 256)   b2 = (const float*)d_in[i];
        else if (s > 100000 && nb < 8) { big_idx[nb] = i; big_sz[nb] = s; nb++; }
    }
    long long min_sz = big_sz[0]; int min_pos = 0;
    for (int i = 1; i < nb; i++)
        if (big_sz[i] < min_sz) { min_sz = big_sz[i]; min_pos = i; }
    index_v = (const int*)d_in[big_idx[min_pos]];
    int n_edge = (int)min_sz;
    bool got_h = false;
    for (int i = 0; i < nb; i++) {
        if (i == min_pos) continue;
        if (!got_h) { h_w = (const float*)d_in[big_idx[i]]; got_h = true; }
        else        { e_vw = (const float*)d_in[big_idx[i]]; }
    }

    float* out = (float*)d_out;
    cudaMemsetAsync(out, 0, (size_t)out_size * sizeof(float));

    static bool attr_set = false;
    if (!attr_set) {
        cudaFuncSetAttribute(msg_mma_kernel,
                             cudaFuncAttributeMaxDynamicSharedMemorySize,
                             SMEM_FLOATS * (int)sizeof(float));
        attr_set = true;
    }
    int ntiles = (n_edge + TILE - 1) / TILE;
    int grid = ntiles < 152 ? ntiles : 152;
    msg_mma_kernel<<<grid, TPB, SMEM_FLOATS * sizeof(float)>>>(
        index_v, h_w, e_vw, W1, b1, W2, b2, out, n_edge);
}

// round 8
// speedup vs baseline: 1.2950x; 1.2950x over previous
#include <cuda_runtime.h>
#include <cuda_fp16.h>
#include <stdint.h>

// MessageFunction via mma.sync m16n8k16 fp16 (fp32 accum), persistent CTAs.
// R8: R6 structure (32 rows/warp, in-register GEMM1->GEMM2 repack) squeezed
//     to <=128 regs for 2 CTAs/SM (4 warps/SMSP): GEMM1 in two 16-row passes,
//     GEMM2 in 8 chunks of 32 cols, cp.async double-buffered staging.

#define TPB   256
#define TILE  256

// ---- smem float offsets (per CTA ~99.25KB) ----
#define OF_W2F 0       // 8192 fl: W2 B-frags uint2[ks(4)][ntg(32)][lane(32)]
#define OF_W1F 8192    // 512 fl : W1 B-frags uint2[nt(8)][lane(32)]
#define OF_B1  8704    // 64
#define OF_B2  8768    // 256
#define OF_E   9024    // 2 x 4096 fl : e tile f32 [256][16], double buffered
#define OF_H   17216   // 2 x 4096 fl : h tile f32 [256][16], double buffered
#define SMEM_FLOATS 25408   // 101632 bytes

__device__ __forceinline__ uint32_t pack_h2(float a, float b) {
    __half2 h = __floats2half2_rn(a, b);
    return *(uint32_t*)&h;
}
__device__ __forceinline__ uint32_t smem_u32(const void* p) {
    uint32_t a;
    asm("{ .reg .u64 t; cvta.to.shared.u64 t, %1; cvt.u32.u64 %0, t; }" : "=r"(a) : "l"(p));
    return a;
}

// Not volatile: pure register computation; let ptxas pipeline it.
#define MMA_F16(d, a, b0, b1) \
    asm("mma.sync.aligned.m16n8k16.row.col.f32.f16.f16.f32 " \
        "{%0,%1,%2,%3}, {%4,%5,%6,%7}, {%8,%9}, {%0,%1,%2,%3};" \
        : "+f"((d)[0]), "+f"((d)[1]), "+f"((d)[2]), "+f"((d)[3]) \
        : "r"((a)[0]), "r"((a)[1]), "r"((a)[2]), "r"((a)[3]), \
          "r"(b0), "r"(b1))

__device__ __forceinline__ void red_add_v2(float* p, float a, float b) {
    asm volatile("red.global.add.v2.f32 [%0], {%1,%2};"
                 :: "l"(p), "f"(a), "f"(b) : "memory");
}
__device__ __forceinline__ void cp16(uint32_t s, const void* g) {
    asm volatile("cp.async.cg.shared.global [%0], [%1], 16;" :: "r"(s), "l"(g));
}
__device__ __forceinline__ void cp_commit() {
    asm volatile("cp.async.commit_group;" ::: "memory");
}
__device__ __forceinline__ void cp_wait_all() {
    asm volatile("cp.async.wait_group 0;" ::: "memory");
}

extern "C" __global__ void __launch_bounds__(TPB, 2)
msg_mma_kernel(const int* __restrict__ index_v,
               const float* __restrict__ h_w,
               const float* __restrict__ e_vw,
               const float* __restrict__ W1,
               const float* __restrict__ b1,
               const float* __restrict__ W2,
               const float* __restrict__ b2,
               float* __restrict__ out,
               int n_edge) {
    extern __shared__ float sm[];
    const uint32_t sb = smem_u32(sm);
    const int tid  = threadIdx.x;
    const int warp = tid >> 5;
    const int lane = tid & 31;
    const int q = lane & 3;       // quad col
    const int g = lane >> 2;      // group row

    // ================= stage weight fragments (once per CTA) =================
    for (int s = tid; s < 4096; s += TPB) {
        int ks = s >> 10, rest = s & 1023, ntg = rest >> 5, ln = rest & 31;
        int qq = ln & 3, gg = ln >> 2;
        int n = ntg * 8 + gg, r0 = ks * 16 + 2 * qq;
        uint2 b;
        b.x = pack_h2(W2[(r0)     * 256 + n], W2[(r0 + 1) * 256 + n]);
        b.y = pack_h2(W2[(r0 + 8) * 256 + n], W2[(r0 + 9) * 256 + n]);
        ((uint2*)(sm + OF_W2F))[s] = b;
    }
    for (int s = tid; s < 256; s += TPB) {
        int nt = s >> 5, ln = s & 31;
        int qq = ln & 3, gg = ln >> 2;
        int n = nt * 8 + gg;
        uint2 b;
        b.x = pack_h2(W1[(2 * qq)     * 64 + n], W1[(2 * qq + 1) * 64 + n]);
        b.y = pack_h2(W1[(2 * qq + 8) * 64 + n], W1[(2 * qq + 9) * 64 + n]);
        ((uint2*)(sm + OF_W1F))[s] = b;
    }
    if (tid < 64)  sm[OF_B1 + tid] = b1[tid];
    if (tid < 256) sm[OF_B2 + tid] = b2[tid];

    const int ntiles = (n_edge + TILE - 1) / TILE;

    // ---- async stage of tile t into buffer bufsel (1 row per thread) ----
    auto stage = [&](int t, int bufsel) {
        const int base = t * TILE;
        const int rem  = n_edge - base;
        const int sr   = tid < rem ? tid : rem - 1;
        const char* ep = (const char*)(e_vw + (size_t)(base + sr) * 16);
        const char* hp = (const char*)(h_w  + (size_t)(base + sr) * 16);
        const uint32_t de = sb + (OF_E + bufsel * 4096 + tid * 16) * 4;
        const uint32_t dh = sb + (OF_H + bufsel * 4096 + tid * 16) * 4;
#pragma unroll
        for (int i = 0; i < 4; i++) {
            cp16(de + 16 * i, ep + 16 * i);
            cp16(dh + 16 * i, hp + 16 * i);
        }
        cp_commit();
    };

    // ---- prologue ----
    if (blockIdx.x < ntiles) stage(blockIdx.x, 0);
    cp_wait_all();
    __syncthreads();

    int it = 0;
    for (int t = blockIdx.x; t < ntiles; t += gridDim.x, it++) {
        const int base = t * TILE;
        const int buf  = it & 1;
        const float* E = sm + OF_E + buf * 4096;
        const float* H = sm + OF_H + buf * 4096;

        // ---- GEMM1 in two 16-row passes; build A-frags ha[2][4][4] ----
        uint32_t ha[2][4][4];
#pragma unroll
        for (int p = 0; p < 2; p++) {
            const int r0 = warp * 32 + p * 16 + g;
            const float* Er = E + r0 * 16;
            uint32_t ea[4];
            {
                float2 c0 = *(const float2*)(Er + 2 * q);
                float2 c1 = *(const float2*)(Er + 8 * 16 + 2 * q);
                float2 c2 = *(const float2*)(Er + 8 + 2 * q);
                float2 c3 = *(const float2*)(Er + 8 * 16 + 8 + 2 * q);
                ea[0] = pack_h2(c0.x, c0.y);
                ea[1] = pack_h2(c1.x, c1.y);
                ea[2] = pack_h2(c2.x, c2.y);
                ea[3] = pack_h2(c3.x, c3.y);
            }
            float acc1[8][4];
#pragma unroll
            for (int nt = 0; nt < 8; nt++)
#pragma unroll
                for (int r = 0; r < 4; r++) acc1[nt][r] = 0.0f;
#pragma unroll
            for (int nt = 0; nt < 8; nt++) {
                uint2 b = ((const uint2*)(sm + OF_W1F))[nt * 32 + lane];
                MMA_F16(acc1[nt], ea, b.x, b.y);
            }
#pragma unroll
            for (int nt = 0; nt < 8; nt++) {
                float2 bb = *(const float2*)(sm + OF_B1 + nt * 8 + 2 * q);
                float v0 = fmaxf(acc1[nt][0] + bb.x, 0.0f);
                float v1 = fmaxf(acc1[nt][1] + bb.y, 0.0f);
                float v2 = fmaxf(acc1[nt][2] + bb.x, 0.0f);
                float v3 = fmaxf(acc1[nt][3] + bb.y, 0.0f);
                int ks = nt >> 1, hi = (nt & 1) * 2;
                ha[p][ks][hi]     = pack_h2(v0, v1);   // row g
                ha[p][ks][hi + 1] = pack_h2(v2, v3);   // row g+8
            }
        }

        // ---- h regs + nodes ----
        float hreg[2][2][4];
        int   node[2][2];
        bool  vld[2][2];
#pragma unroll
        for (int mt = 0; mt < 2; mt++)
#pragma unroll
            for (int rr = 0; rr < 2; rr++) {
                const int row = warp * 32 + mt * 16 + g + rr * 8;
                const float* Hr = H + row * 16;
                float2 h0 = *(const float2*)(Hr + 2 * q);
                float2 h1 = *(const float2*)(Hr + 8 + 2 * q);
                hreg[mt][rr][0] = h0.x; hreg[mt][rr][1] = h0.y;
                hreg[mt][rr][2] = h1.x; hreg[mt][rr][3] = h1.y;
                const int ge = base + row;
                vld[mt][rr]  = ge < n_edge;
                node[mt][rr] = vld[mt][rr] ? __ldg(index_v + ge) : 0;
            }

        // ---- kick off next-tile async staging ----
        const int tn = t + gridDim.x;
        if (tn < ntiles) stage(tn, buf ^ 1);

        // ---- GEMM2 + epilogue, 8 chunks of 32 cols (m = 2c, 2c+1) ----
#pragma unroll
        for (int c = 0; c < 8; c++) {
            float acc[2][4][4];
#pragma unroll
            for (int mt = 0; mt < 2; mt++)
#pragma unroll
                for (int nt = 0; nt < 4; nt++)
#pragma unroll
                    for (int r = 0; r < 4; r++) acc[mt][nt][r] = 0.0f;
#pragma unroll
            for (int ks = 0; ks < 4; ks++)
#pragma unroll
                for (int nt = 0; nt < 4; nt++) {
                    uint2 b = ((const uint2*)(sm + OF_W2F))[(ks * 32 + c * 4 + nt) * 32 + lane];
                    MMA_F16(acc[0][nt], ha[0][ks], b.x, b.y);
                    MMA_F16(acc[1][nt], ha[1][ks], b.x, b.y);
                }
            float pacc[2][2][2];
#pragma unroll
            for (int mt = 0; mt < 2; mt++)
#pragma unroll
                for (int rr = 0; rr < 2; rr++) {
                    pacc[mt][rr][0] = 0.0f; pacc[mt][rr][1] = 0.0f;
                }
#pragma unroll
            for (int nt = 0; nt < 4; nt++) {
                const int ntg = c * 4 + nt;
                float2 bb = *(const float2*)(sm + OF_B2 + ntg * 8 + 2 * q);
                const int hb = (nt & 1) * 2;
                const int ml = nt >> 1;
#pragma unroll
                for (int mt = 0; mt < 2; mt++) {
                    pacc[mt][0][ml] = fmaf(acc[mt][nt][0] + bb.x, hreg[mt][0][hb],     pacc[mt][0][ml]);
                    pacc[mt][0][ml] = fmaf(acc[mt][nt][1] + bb.y, hreg[mt][0][hb + 1], pacc[mt][0][ml]);
                    pacc[mt][1][ml] = fmaf(acc[mt][nt][2] + bb.x, hreg[mt][1][hb],     pacc[mt][1][ml]);
                    pacc[mt][1][ml] = fmaf(acc[mt][nt][3] + bb.y, hreg[mt][1][hb + 1], pacc[mt][1][ml]);
                }
            }
#pragma unroll
            for (int mt = 0; mt < 2; mt++)
#pragma unroll
                for (int rr = 0; rr < 2; rr++) {
#pragma unroll
                    for (int ml = 0; ml < 2; ml++) {
                        float v = pacc[mt][rr][ml];
                        v += __shfl_xor_sync(0xFFFFFFFFu, v, 1);
                        v += __shfl_xor_sync(0xFFFFFFFFu, v, 2);
                        pacc[mt][rr][ml] = v;
                    }
                    if (q == 0 && vld[mt][rr]) {
                        red_add_v2(out + (size_t)node[mt][rr] * 16 + 2 * c,
                                   pacc[mt][rr][0], pacc[mt][rr][1]);
                    }
                }
        }

        cp_wait_all();     // next-tile staging landed
        __syncthreads();   // all reads of current buffers done CTA-wide
    }
}

// ---------------- launch ----------------
extern "C" void kernel_launch(void* const* d_in, const int* in_sizes, int n_in,
                              void* d_out, int out_size) {
    const int*   index_v = nullptr;
    const float* h_w = nullptr;
    const float* e_vw = nullptr;
    const float* W1 = nullptr;
    const float* b1 = nullptr;
    const float* W2 = nullptr;
    const float* b2 = nullptr;

    int big_idx[8]; long long big_sz[8]; int nb = 0;
    for (int i = 0; i < n_in; i++) {
        long long s = in_sizes[i];
        if (s == 1024)       W1 = (const float*)d_in[i];
        else if (s == 64)    b1 = (const float*)d_in[i];
        else if (s == 16384) W2 = (const float*)d_in[i];
        else if (s == 256)   b2 = (const float*)d_in[i];
        else if (s > 100000 && nb < 8) { big_idx[nb] = i; big_sz[nb] = s; nb++; }
    }
    long long min_sz = big_sz[0]; int min_pos = 0;
    for (int i = 1; i < nb; i++)
        if (big_sz[i] < min_sz) { min_sz = big_sz[i]; min_pos = i; }
    index_v = (const int*)d_in[big_idx[min_pos]];
    int n_edge = (int)min_sz;
    bool got_h = false;
    for (int i = 0; i < nb; i++) {
        if (i == min_pos) continue;
        if (!got_h) { h_w = (const float*)d_in[big_idx[i]]; got_h = true; }
        else        { e_vw = (const float*)d_in[big_idx[i]]; }
    }

    float* out = (float*)d_out;
    cudaMemsetAsync(out, 0, (size_t)out_size * sizeof(float));

    static bool attr_set = false;
    if (!attr_set) {
        cudaFuncSetAttribute(msg_mma_kernel,
                             cudaFuncAttributeMaxDynamicSharedMemorySize,
                             SMEM_FLOATS * (int)sizeof(float));
        attr_set = true;
    }
    int ntiles = (n_edge + TILE - 1) / TILE;
    int grid = ntiles < 304 ? ntiles : 304;   // 2 CTAs/SM x 152 SMs
    msg_mma_kernel<<<grid, TPB, SMEM_FLOATS * sizeof(float)>>>(
        index_v, h_w, e_vw, W1, b1, W2, b2, out, n_edge);
}